// round 9
// baseline (speedup 1.0000x reference)
#include <cuda_runtime.h>
#include <math.h>

#define N_NODES 100000
#define N_EDGES 1600000
#define D 128
#define KC 32   // K-chunk for GEMM smem staging

// ---------------- static device scratch (no allocations allowed) ----------------
__device__ int    g_is64;                     // 1 if edge_index is int64, 0 if int32
__device__ int    g_deg[N_NODES];
__device__ int    g_off[N_NODES];
__device__ int    g_cur[N_NODES];
__device__ float  g_dis[N_NODES];             // deg^-1/2
__device__ int    g_scol[N_EDGES];            // edge cols grouped by dest row
__device__ float4 g_h4[(size_t)N_NODES * 32]; // x @ neighbor_weight, 16B-aligned
__device__ int    g_bsum[128];
__device__ int    g_bpre[128];

// ---------------- dtype detection ----------------
// int64 little-endian values in [0, N_NODES) have all-zero high words.
// int32 data at odd word positions is a random index (zero w.p. 1e-5 each).
__global__ void k_detect(const unsigned int* __restrict__ w) {
    if (threadIdx.x == 0 && blockIdx.x == 0) {
        int is64 = 1;
        for (int i = 0; i < 64; i++)
            if (w[2 * i + 1] != 0u) { is64 = 0; break; }
        g_is64 = is64;
    }
}

__device__ __forceinline__ int clampN(int v) {
    v = v < 0 ? 0 : v;
    return v >= N_NODES ? N_NODES - 1 : v;
}

// ---------------- preprocessing ----------------
__global__ void k_zero_deg() {
    int i = blockIdx.x * blockDim.x + threadIdx.x;
    if (i < N_NODES) g_deg[i] = 0;
}

__global__ void k_count(const void* __restrict__ eidx) {
    int e = blockIdx.x * blockDim.x + threadIdx.x;
    if (e < N_EDGES) {
        int r;
        if (g_is64) r = (int)((const long long*)eidx)[e];
        else        r = ((const int*)eidx)[e];
        atomicAdd(&g_deg[clampN(r)], 1);
    }
}

// block-wise exclusive scan of g_deg (98 blocks x 1024)
__global__ void k_scanA() {
    __shared__ int s[1024];
    int tid = threadIdx.x;
    int i = blockIdx.x * 1024 + tid;
    int v = (i < N_NODES) ? g_deg[i] : 0;
    s[tid] = v;
    __syncthreads();
    for (int d = 1; d < 1024; d <<= 1) {
        int t = (tid >= d) ? s[tid - d] : 0;
        __syncthreads();
        s[tid] += t;
        __syncthreads();
    }
    if (i < N_NODES) g_off[i] = s[tid] - v;   // exclusive within block
    if (tid == 1023) g_bsum[blockIdx.x] = s[1023];
}

__global__ void k_scanB() {
    if (threadIdx.x == 0) {
        int acc = 0;
        for (int b = 0; b < 98; b++) { g_bpre[b] = acc; acc += g_bsum[b]; }
    }
}

__global__ void k_scanC() {
    int i = blockIdx.x * 1024 + threadIdx.x;
    if (i < N_NODES) {
        int o = g_off[i] + g_bpre[blockIdx.x];
        g_off[i] = o;
        g_cur[i] = o;
        g_dis[i] = rsqrtf((float)g_deg[i]);   // deg==0 -> inf, matches deg**-0.5
    }
}

__global__ void k_scatter(const void* __restrict__ eidx) {
    int e = blockIdx.x * blockDim.x + threadIdx.x;
    if (e < N_EDGES) {
        int r, c;
        if (g_is64) {
            const long long* p = (const long long*)eidx;
            r = (int)p[e];
            c = (int)p[N_EDGES + e];
        } else {
            const int* p = (const int*)eidx;
            r = p[e];
            c = p[N_EDGES + e];
        }
        r = clampN(r);
        c = clampN(c);
        int pos = atomicAdd(&g_cur[r], 1);
        g_scol[pos] = c;
    }
}

// ---------------- fused dual GEMM: out = x@Ws + bias, g_h = x@Wn ----------------
// Tile: 128 rows x (128+128) cols, 512 threads (16 warps), K chunked by 32.
// Static smem = 3 * 32*128 * 4B = 48 KB exactly.
// Warp w owns rows [8w, 8w+8); lane owns cols [4*lane, 4*lane+4) of each matrix.
__global__ void __launch_bounds__(512)
k_gemm(const float* __restrict__ x,
       const float* __restrict__ Ws,
       const float* __restrict__ Wn,
       const float* __restrict__ bias,
       float* __restrict__ out) {
    __shared__ float sWs[KC * D];   // [kk][c]
    __shared__ float sWn[KC * D];   // [kk][c]
    __shared__ float sX [D * KC];   // [r][kk]

    int tid = threadIdx.x;
    int rowBase = blockIdx.x * 128;
    int warp = tid >> 5;
    int lane = tid & 31;
    int rb = warp * 8;
    int cb = lane * 4;

    float accS[8][4], accN[8][4];
#pragma unroll
    for (int i = 0; i < 8; i++)
#pragma unroll
        for (int j = 0; j < 4; j++) { accS[i][j] = 0.f; accN[i][j] = 0.f; }

    for (int kc = 0; kc < D; kc += KC) {
        __syncthreads();   // protect previous chunk's reads
        // stage weight chunks: rows [kc, kc+KC) of each 128x128 matrix
        {
            const float4* a = (const float4*)(Ws + kc * D);
            const float4* b = (const float4*)(Wn + kc * D);
            float4* sa = (float4*)sWs;
            float4* sb = (float4*)sWn;
            for (int i = tid; i < KC * D / 4; i += 512) { sa[i] = a[i]; sb[i] = b[i]; }
        }
        // stage x chunk: rows [rowBase, rowBase+128), cols [kc, kc+KC)
        for (int i = tid; i < 128 * (KC / 4); i += 512) {
            int r = i >> 3;
            int q = i & 7;
            int gr = rowBase + r;
            float4 v = (gr < N_NODES)
                ? ((const float4*)x)[(size_t)gr * (D / 4) + (kc / 4) + q]
                : make_float4(0.f, 0.f, 0.f, 0.f);
            ((float4*)sX)[r * (KC / 4) + q] = v;
        }
        __syncthreads();

#pragma unroll 4
        for (int kk = 0; kk < KC; kk++) {
            float4 wa = *(const float4*)&sWs[kk * D + cb];
            float4 wb = *(const float4*)&sWn[kk * D + cb];
#pragma unroll
            for (int i = 0; i < 8; i++) {
                float xv = sX[(rb + i) * KC + kk];   // warp-broadcast LDS
                accS[i][0] += xv * wa.x; accS[i][1] += xv * wa.y;
                accS[i][2] += xv * wa.z; accS[i][3] += xv * wa.w;
                accN[i][0] += xv * wb.x; accN[i][1] += xv * wb.y;
                accN[i][2] += xv * wb.z; accN[i][3] += xv * wb.w;
            }
        }
    }

    float4 bv = ((const float4*)bias)[lane];
#pragma unroll
    for (int i = 0; i < 8; i++) {
        int gr = rowBase + rb + i;
        if (gr < N_NODES) {
            float4 o;
            o.x = accS[i][0] + bv.x; o.y = accS[i][1] + bv.y;
            o.z = accS[i][2] + bv.z; o.w = accS[i][3] + bv.w;
            ((float4*)out)[(size_t)gr * 32 + lane] = o;
            float4 hh;
            hh.x = accN[i][0]; hh.y = accN[i][1];
            hh.z = accN[i][2]; hh.w = accN[i][3];
            g_h4[(size_t)gr * 32 + lane] = hh;
        }
    }
}

// ---------------- SpMM: one warp per row, gather-accumulate (no atomics) --------
__global__ void __launch_bounds__(256)
k_spmm(float* __restrict__ out) {
    int gw = (blockIdx.x * blockDim.x + threadIdx.x) >> 5;
    int lane = threadIdx.x & 31;
    if (gw >= N_NODES) return;
    int r = gw;
    int beg = g_off[r];
    int cnt = g_deg[r];
    float disr = g_dis[r];

    float ax = 0.f, ay = 0.f, az = 0.f, aw = 0.f;
    int e = 0;
    // 2-way unroll: independent load chains raise MLP
    for (; e + 1 < cnt; e += 2) {
        int c0 = g_scol[beg + e];
        int c1 = g_scol[beg + e + 1];
        float n0 = disr * g_dis[c0];
        float n1 = disr * g_dis[c1];
        float4 h0 = g_h4[(size_t)c0 * 32 + lane];
        float4 h1 = g_h4[(size_t)c1 * 32 + lane];
        ax += n0 * h0.x + n1 * h1.x;
        ay += n0 * h0.y + n1 * h1.y;
        az += n0 * h0.z + n1 * h1.z;
        aw += n0 * h0.w + n1 * h1.w;
    }
    if (e < cnt) {
        int c = g_scol[beg + e];
        float nrm = disr * g_dis[c];
        float4 hv = g_h4[(size_t)c * 32 + lane];
        ax += nrm * hv.x; ay += nrm * hv.y;
        az += nrm * hv.z; aw += nrm * hv.w;
    }
    float4* op = (float4*)out + (size_t)r * 32 + lane;
    float4 o = *op;               // already holds self_support + bias
    o.x += ax; o.y += ay; o.z += az; o.w += aw;
    *op = o;
}

// ---------------- launch ----------------
extern "C" void kernel_launch(void* const* d_in, const int* in_sizes, int n_in,
                              void* d_out, int out_size) {
    const float* x    = (const float*)d_in[0];
    const void*  eidx = d_in[1];                 // int32 or int64 — detected on device
    const float* Ws   = (const float*)d_in[2];
    const float* Wn   = (const float*)d_in[3];
    const float* bias = (const float*)d_in[4];
    float*       out  = (float*)d_out;

    k_detect<<<1, 32>>>((const unsigned int*)eidx);
    k_zero_deg<<<(N_NODES + 255) / 256, 256>>>();
    k_count<<<(N_EDGES + 255) / 256, 256>>>(eidx);
    k_scanA<<<98, 1024>>>();
    k_scanB<<<1, 32>>>();
    k_scanC<<<98, 1024>>>();
    k_scatter<<<(N_EDGES + 255) / 256, 256>>>(eidx);
    k_gemm<<<(N_NODES + 127) / 128, 512>>>(x, Ws, Wn, bias, out);
    k_spmm<<<(N_NODES * 32 + 255) / 256, 256>>>(out);
}

// round 10
// speedup vs baseline: 1.0607x; 1.0607x over previous
#include <cuda_runtime.h>
#include <math.h>

#define N_NODES 100000
#define N_EDGES 1600000
#define D 128
#define KC 32   // K-chunk for GEMM smem staging

// ---------------- static device scratch (no allocations allowed) ----------------
__device__ int    g_is64;                     // 1 if edge_index is int64, 0 if int32
__device__ int    g_deg[N_NODES];
__device__ int    g_off[N_NODES];
__device__ int    g_cur[N_NODES];
__device__ float  g_dis[N_NODES];             // deg^-1/2
__device__ int    g_scol[N_EDGES];            // edge cols grouped by dest row
__device__ float4 g_h4[(size_t)N_NODES * 32]; // x @ neighbor_weight, 16B-aligned
__device__ int    g_bsum[128];
__device__ int    g_bpre[128];

__device__ __forceinline__ int clampN(int v) {
    v = v < 0 ? 0 : v;
    return v >= N_NODES ? N_NODES - 1 : v;
}

// ---------------- zero degrees + dtype detection (fused) ----------------
// int64 little-endian values in [0, N_NODES) have all-zero high words.
// int32 data at odd word positions is a random index (zero w.p. 1e-5 each).
__global__ void k_zero_detect(const unsigned int* __restrict__ w) {
    int i = blockIdx.x * blockDim.x + threadIdx.x;
    if (i < N_NODES) g_deg[i] = 0;
    if (i == 0) {
        int is64 = 1;
        for (int j = 0; j < 64; j++)
            if (w[2 * j + 1] != 0u) { is64 = 0; break; }
        g_is64 = is64;
    }
}

// ---------------- degree count: 4 edges per thread, vector loads ----------------
__global__ void k_count(const void* __restrict__ eidx) {
    int q = blockIdx.x * blockDim.x + threadIdx.x;   // quad index
    if (q < N_EDGES / 4) {
        int r0, r1, r2, r3;
        if (g_is64) {
            longlong4 v = ((const longlong4*)eidx)[q];
            r0 = (int)v.x; r1 = (int)v.y; r2 = (int)v.z; r3 = (int)v.w;
        } else {
            int4 v = ((const int4*)eidx)[q];
            r0 = v.x; r1 = v.y; r2 = v.z; r3 = v.w;
        }
        atomicAdd(&g_deg[clampN(r0)], 1);
        atomicAdd(&g_deg[clampN(r1)], 1);
        atomicAdd(&g_deg[clampN(r2)], 1);
        atomicAdd(&g_deg[clampN(r3)], 1);
    }
}

// block-wise exclusive scan of g_deg (98 blocks x 1024)
__global__ void k_scanA() {
    __shared__ int s[1024];
    int tid = threadIdx.x;
    int i = blockIdx.x * 1024 + tid;
    int v = (i < N_NODES) ? g_deg[i] : 0;
    s[tid] = v;
    __syncthreads();
    for (int d = 1; d < 1024; d <<= 1) {
        int t = (tid >= d) ? s[tid - d] : 0;
        __syncthreads();
        s[tid] += t;
        __syncthreads();
    }
    if (i < N_NODES) g_off[i] = s[tid] - v;   // exclusive within block
    if (tid == 1023) g_bsum[blockIdx.x] = s[1023];
}

__global__ void k_scanB() {
    if (threadIdx.x == 0) {
        int acc = 0;
        for (int b = 0; b < 98; b++) { g_bpre[b] = acc; acc += g_bsum[b]; }
    }
}

__global__ void k_scanC() {
    int i = blockIdx.x * 1024 + threadIdx.x;
    if (i < N_NODES) {
        int o = g_off[i] + g_bpre[blockIdx.x];
        g_off[i] = o;
        g_cur[i] = o;
        g_dis[i] = rsqrtf((float)g_deg[i]);   // deg==0 -> inf, matches deg**-0.5
    }
}

__global__ void k_scatter(const void* __restrict__ eidx) {
    int e = blockIdx.x * blockDim.x + threadIdx.x;
    if (e < N_EDGES) {
        int r, c;
        if (g_is64) {
            const long long* p = (const long long*)eidx;
            r = (int)p[e];
            c = (int)p[N_EDGES + e];
        } else {
            const int* p = (const int*)eidx;
            r = p[e];
            c = p[N_EDGES + e];
        }
        r = clampN(r);
        c = clampN(c);
        int pos = atomicAdd(&g_cur[r], 1);
        g_scol[pos] = c;
    }
}

// ---------------- packed f32x2 FMA helpers (Blackwell FFMA2) ----------------
__device__ __forceinline__ void fma2(unsigned long long& acc,
                                     unsigned long long a,
                                     unsigned long long b) {
    asm("fma.rn.f32x2 %0, %1, %2, %0;" : "+l"(acc) : "l"(a), "l"(b));
}
__device__ __forceinline__ unsigned long long dup2(float v) {
    unsigned long long p;
    asm("mov.b64 %0, {%1, %1};" : "=l"(p) : "f"(v));
    return p;
}
__device__ __forceinline__ float2 unpk2(unsigned long long v) {
    float lo, hi;
    asm("mov.b64 {%0, %1}, %2;" : "=f"(lo), "=f"(hi) : "l"(v));
    return make_float2(lo, hi);
}

// ---------------- fused dual GEMM: out = x@Ws + bias, g_h = x@Wn ----------------
// Tile: 128 rows x (128+128) cols, 512 threads (16 warps), K chunked by 32.
// Static smem = 3 * 32*128 * 4B = 48 KB.
// Warp w owns rows [8w, 8w+8); lane owns cols [4*lane, 4*lane+4) of each matrix,
// held as 2 packed f32x2 accumulators per matrix per row.
__global__ void __launch_bounds__(512)
k_gemm(const float* __restrict__ x,
       const float* __restrict__ Ws,
       const float* __restrict__ Wn,
       const float* __restrict__ bias,
       float* __restrict__ out) {
    __shared__ float sWs[KC * D];   // [kk][c]
    __shared__ float sWn[KC * D];   // [kk][c]
    __shared__ float sX [D * KC];   // [r][kk]

    int tid = threadIdx.x;
    int rowBase = blockIdx.x * 128;
    int warp = tid >> 5;
    int lane = tid & 31;
    int rb = warp * 8;
    int cb = lane * 4;

    unsigned long long accS[8][2], accN[8][2];
#pragma unroll
    for (int i = 0; i < 8; i++) {
        accS[i][0] = 0ull; accS[i][1] = 0ull;
        accN[i][0] = 0ull; accN[i][1] = 0ull;
    }

    for (int kc = 0; kc < D; kc += KC) {
        __syncthreads();   // protect previous chunk's reads
        // stage weight chunks: rows [kc, kc+KC) of each 128x128 matrix
        {
            const float4* a = (const float4*)(Ws + kc * D);
            const float4* b = (const float4*)(Wn + kc * D);
            float4* sa = (float4*)sWs;
            float4* sb = (float4*)sWn;
            for (int i = tid; i < KC * D / 4; i += 512) { sa[i] = a[i]; sb[i] = b[i]; }
        }
        // stage x chunk: rows [rowBase, rowBase+128), cols [kc, kc+KC)
        for (int i = tid; i < 128 * (KC / 4); i += 512) {
            int r = i >> 3;
            int q = i & 7;
            int gr = rowBase + r;
            float4 v = (gr < N_NODES)
                ? ((const float4*)x)[(size_t)gr * (D / 4) + (kc / 4) + q]
                : make_float4(0.f, 0.f, 0.f, 0.f);
            ((float4*)sX)[r * (KC / 4) + q] = v;
        }
        __syncthreads();

#pragma unroll 4
        for (int kk = 0; kk < KC; kk++) {
            // weight pairs pre-packed: 4 contiguous floats = 2 f32x2 operands
            ulonglong2 wa = *(const ulonglong2*)&sWs[kk * D + cb];
            ulonglong2 wb = *(const ulonglong2*)&sWn[kk * D + cb];
#pragma unroll
            for (int i = 0; i < 8; i++) {
                unsigned long long xv = dup2(sX[(rb + i) * KC + kk]); // bcast LDS
                fma2(accS[i][0], xv, wa.x);
                fma2(accS[i][1], xv, wa.y);
                fma2(accN[i][0], xv, wb.x);
                fma2(accN[i][1], xv, wb.y);
            }
        }
    }

    float4 bv = ((const float4*)bias)[lane];
#pragma unroll
    for (int i = 0; i < 8; i++) {
        int gr = rowBase + rb + i;
        if (gr < N_NODES) {
            float2 s0 = unpk2(accS[i][0]);
            float2 s1 = unpk2(accS[i][1]);
            float4 o;
            o.x = s0.x + bv.x; o.y = s0.y + bv.y;
            o.z = s1.x + bv.z; o.w = s1.y + bv.w;
            ((float4*)out)[(size_t)gr * 32 + lane] = o;
            float2 n0 = unpk2(accN[i][0]);
            float2 n1 = unpk2(accN[i][1]);
            float4 hh;
            hh.x = n0.x; hh.y = n0.y; hh.z = n1.x; hh.w = n1.y;
            g_h4[(size_t)gr * 32 + lane] = hh;
        }
    }
}

// ---------------- SpMM: one warp per row, gather-accumulate (no atomics) --------
__global__ void __launch_bounds__(256)
k_spmm(float* __restrict__ out) {
    int gw = (blockIdx.x * blockDim.x + threadIdx.x) >> 5;
    int lane = threadIdx.x & 31;
    if (gw >= N_NODES) return;
    int r = gw;
    int beg = g_off[r];
    int cnt = g_deg[r];
    float disr = g_dis[r];

    float ax = 0.f, ay = 0.f, az = 0.f, aw = 0.f;
    int e = 0;
    // 2-way unroll: independent load chains raise MLP
    for (; e + 1 < cnt; e += 2) {
        int c0 = g_scol[beg + e];
        int c1 = g_scol[beg + e + 1];
        float n0 = disr * g_dis[c0];
        float n1 = disr * g_dis[c1];
        float4 h0 = g_h4[(size_t)c0 * 32 + lane];
        float4 h1 = g_h4[(size_t)c1 * 32 + lane];
        ax += n0 * h0.x + n1 * h1.x;
        ay += n0 * h0.y + n1 * h1.y;
        az += n0 * h0.z + n1 * h1.z;
        aw += n0 * h0.w + n1 * h1.w;
    }
    if (e < cnt) {
        int c = g_scol[beg + e];
        float nrm = disr * g_dis[c];
        float4 hv = g_h4[(size_t)c * 32 + lane];
        ax += nrm * hv.x; ay += nrm * hv.y;
        az += nrm * hv.z; aw += nrm * hv.w;
    }
    float4* op = (float4*)out + (size_t)r * 32 + lane;
    float4 o = *op;               // already holds self_support + bias
    o.x += ax; o.y += ay; o.z += az; o.w += aw;
    *op = o;
}

// ---------------- launch ----------------
extern "C" void kernel_launch(void* const* d_in, const int* in_sizes, int n_in,
                              void* d_out, int out_size) {
    const float* x    = (const float*)d_in[0];
    const void*  eidx = d_in[1];                 // int32 or int64 — detected on device
    const float* Ws   = (const float*)d_in[2];
    const float* Wn   = (const float*)d_in[3];
    const float* bias = (const float*)d_in[4];
    float*       out  = (float*)d_out;

    k_zero_detect<<<(N_NODES + 255) / 256, 256>>>((const unsigned int*)eidx);
    k_count<<<(N_EDGES / 4 + 255) / 256, 256>>>(eidx);
    k_scanA<<<98, 1024>>>();
    k_scanB<<<1, 32>>>();
    k_scanC<<<98, 1024>>>();
    k_scatter<<<(N_EDGES + 255) / 256, 256>>>(eidx);
    k_gemm<<<(N_NODES + 127) / 128, 512>>>(x, Ws, Wn, bias, out);
    k_spmm<<<(N_NODES * 32 + 255) / 256, 256>>>(out);
}